// round 1
// baseline (speedup 1.0000x reference)
#include <cuda_runtime.h>
#include <cuda_bf16.h>

// Fused shifted-window attention (Swin block) for:
// B=4, C=192, H=W=256, window=8 (N=64 tokens), shift=4, heads=8, hd=24.
// One CTA per window (4096 CTAs, 256 threads). Everything stays in SMEM:
//   gather(x, shifted) -> QKV GEMM -> per-head attn (+rel-pos bias, shift mask,
//   softmax) -> proj GEMM -> +residual -> scatter to output.

constexpr int Cc     = 192;
constexpr int Nn     = 64;
constexpr int HEADS_ = 8;
constexpr int HD_    = 24;
constexpr int TPB    = 256;

// SMEM layout (floats):
//  xsh  [192][64]   gathered window, transposed [chan][token]
//  aout [192][64]   attention output, transposed [chan][token]
//  wsh  [16][196]   weight k-tile (transposed, padded)
//  Ssh  [64][65]    per-head scores
//  rpbs [1800]      rel-pos bias table (225 x 8)
//  rinv [64]        softmax 1/sum
// then bf16: qsh[8][24][64], ksh[8][24][64], vsh[8][64][24]
constexpr int SMEM_FLOATS = Cc*Nn + Cc*Nn + 16*196 + 64*65 + 1800 + 64;
constexpr int SMEM_BYTES  = SMEM_FLOATS*4 + 3*(HEADS_*HD_*Nn)*2;   // 208672

__device__ __forceinline__ void load4bf(float* o, const __nv_bfloat16* p) {
    const __nv_bfloat162* p2 = (const __nv_bfloat162*)p;
    float2 a = __bfloat1622float2(p2[0]);
    float2 b = __bfloat1622float2(p2[1]);
    o[0] = a.x; o[1] = a.y; o[2] = b.x; o[3] = b.y;
}

__global__ void __launch_bounds__(TPB, 1)
swin_fused(const float* __restrict__ x,
           const float* __restrict__ qkv_w,
           const float* __restrict__ qkv_b,
           const float* __restrict__ proj_w,
           const float* __restrict__ proj_b,
           const float* __restrict__ rpb,
           float* __restrict__ out)
{
    extern __shared__ float sm[];
    float* xsh  = sm;
    float* aout = xsh  + Cc*Nn;
    float* wsh  = aout + Cc*Nn;
    float* Ssh  = wsh  + 16*196;
    float* rpbs = Ssh  + 64*65;
    float* rinv = rpbs + 1800;
    __nv_bfloat16* qsh = (__nv_bfloat16*)(rinv + 64);
    __nv_bfloat16* ksh = qsh + HEADS_*HD_*Nn;
    __nv_bfloat16* vsh = ksh + HEADS_*HD_*Nn;

    const int tid = threadIdx.x;
    const int win = blockIdx.x;
    const int b   = win >> 10;          // / 1024
    const int wr  = (win >> 5) & 31;
    const int wc  = win & 31;
    const int hbase = wr*8 + 4;         // +shift (roll -4 forward)
    const int wbase = wc*8 + 4;

    // preload rel-pos bias table
    for (int i = tid; i < 1800; i += TPB) rpbs[i] = rpb[i];

    // gather shifted window x -> xsh[c][t]
    {
        const float* xb = x + ((b*Cc) << 16);
        for (int idx = tid; idx < Cc*Nn; idx += TPB) {
            int c = idx >> 6, t = idx & 63;
            int hh = (hbase + (t >> 3)) & 255;
            int ww = (wbase + (t & 7)) & 255;
            xsh[idx] = xb[(c << 16) + (hh << 8) + ww];
        }
    }
    __syncthreads();

    const int tx = tid & 15;    // token dim
    const int ty = tid >> 4;    // out dim
    const int t0 = tx << 2;     // 4 tokens
    const int o0 = ty * 12;     // 12 outs (local to 192-chunk)

    // ===================== QKV GEMM: 3 chunks of 192 outs =====================
    for (int oc = 0; oc < 3; ++oc) {
        float acc[4][12];
        #pragma unroll
        for (int i = 0; i < 4; ++i)
            #pragma unroll
            for (int j = 0; j < 12; ++j) acc[i][j] = 0.f;

        const float* Wbase = qkv_w + oc*192*Cc;
        for (int k0 = 0; k0 < Cc; k0 += 16) {
            __syncthreads();
            {   // load W tile transposed: wsh[kk][ol] = W[oc*192+ol][k0+kk]
                const int kk   = (tid & 3) << 2;
                const int orow = tid >> 2;
                #pragma unroll
                for (int it = 0; it < 3; ++it) {
                    int ol = it*64 + orow;
                    float4 wv = *(const float4*)&Wbase[ol*Cc + k0 + kk];
                    float* dst = &wsh[kk*196 + ol];
                    dst[0]   = wv.x; dst[196] = wv.y;
                    dst[392] = wv.z; dst[588] = wv.w;
                }
            }
            __syncthreads();
            #pragma unroll 4
            for (int kk = 0; kk < 16; ++kk) {
                float4 xv = *(const float4*)&xsh[(k0+kk)*64 + t0];
                const float* wp = &wsh[kk*196 + o0];
                float4 w0 = *(const float4*)(wp);
                float4 w1 = *(const float4*)(wp+4);
                float4 w2 = *(const float4*)(wp+8);
                float wv[12] = {w0.x,w0.y,w0.z,w0.w, w1.x,w1.y,w1.z,w1.w,
                                w2.x,w2.y,w2.z,w2.w};
                float xa[4]  = {xv.x, xv.y, xv.z, xv.w};
                #pragma unroll
                for (int i = 0; i < 4; ++i)
                    #pragma unroll
                    for (int j = 0; j < 12; ++j)
                        acc[i][j] += xa[i]*wv[j];
            }
        }
        // epilogue: +bias, store to q/k/v smem (bf16)
        #pragma unroll
        for (int j = 0; j < 12; ++j) {
            int og = o0 + j;
            float bv = qkv_b[oc*192 + og];
            int h = og / 24;
            int d = og - h*24;
            #pragma unroll
            for (int i = 0; i < 4; ++i) {
                float v = acc[i][j] + bv;
                int t = t0 + i;
                if (oc == 0)      qsh[(h*24 + d)*64 + t] = __float2bfloat16(v);
                else if (oc == 1) ksh[(h*24 + d)*64 + t] = __float2bfloat16(v);
                else              vsh[(h*64 + t)*24 + d] = __float2bfloat16(v);
            }
        }
    }
    __syncthreads();

    // ===================== attention (8 heads, sequential) =====================
    const float scale = 0.2041241452319315f;   // 24^-0.5
    const bool er = (wr == 31), ec = (wc == 31);
    const int j0 = ty << 2;

    int regi[4], regj[4];
    #pragma unroll
    for (int i = 0; i < 4; ++i) {
        int t = t0 + i;
        regi[i] = (er ? (((t>>3) < 4) ? 3 : 6) : 0)
                + (ec ? (((t&7)  < 4) ? 1 : 2) : 0);
    }
    #pragma unroll
    for (int j = 0; j < 4; ++j) {
        int t = j0 + j;
        regj[j] = (er ? (((t>>3) < 4) ? 3 : 6) : 0)
                + (ec ? (((t&7)  < 4) ? 1 : 2) : 0);
    }

    for (int h = 0; h < HEADS_; ++h) {
        // ---- S = q @ k^T ----
        float s[4][4];
        #pragma unroll
        for (int i = 0; i < 4; ++i)
            #pragma unroll
            for (int j = 0; j < 4; ++j) s[i][j] = 0.f;

        const __nv_bfloat16* qp = qsh + h*HD_*Nn;
        const __nv_bfloat16* kp = ksh + h*HD_*Nn;
        #pragma unroll 4
        for (int d = 0; d < HD_; ++d) {
            float qa[4], ka[4];
            load4bf(qa, qp + d*64 + t0);
            load4bf(ka, kp + d*64 + j0);
            #pragma unroll
            for (int i = 0; i < 4; ++i)
                #pragma unroll
                for (int j = 0; j < 4; ++j) s[i][j] += qa[i]*ka[j];
        }
        #pragma unroll
        for (int i = 0; i < 4; ++i) {
            int ti_ = t0 + i;
            int yi = ti_ >> 3, xi = ti_ & 7;
            #pragma unroll
            for (int j = 0; j < 4; ++j) {
                int tj_ = j0 + j;
                int idx = (yi - (tj_>>3) + 7)*15 + (xi - (tj_&7) + 7);
                float bias = rpbs[idx*8 + h];
                float m = (regi[i] != regj[j]) ? -100.f : 0.f;
                Ssh[ti_*65 + tj_] = s[i][j]*scale + bias + m;
            }
        }
        __syncthreads();

        // ---- softmax (4 threads per row) ----
        {
            int r = tid >> 2, p = tid & 3;
            float* row = Ssh + r*65 + p*16;
            float mx = row[0];
            #pragma unroll
            for (int c = 1; c < 16; ++c) mx = fmaxf(mx, row[c]);
            mx = fmaxf(mx, __shfl_xor_sync(0xffffffffu, mx, 1));
            mx = fmaxf(mx, __shfl_xor_sync(0xffffffffu, mx, 2));
            float sum = 0.f;
            #pragma unroll
            for (int c = 0; c < 16; ++c) {
                float e = __expf(row[c] - mx);
                row[c] = e;
                sum += e;
            }
            sum += __shfl_xor_sync(0xffffffffu, sum, 1);
            sum += __shfl_xor_sync(0xffffffffu, sum, 2);
            if (p == 0) rinv[r] = 1.f / sum;
        }
        __syncthreads();

        // ---- O = P @ v  (store transposed into aout[c][t]) ----
        {
            int i  = tid & 63;
            int dg = tid >> 6;          // 0..3
            int d0 = dg*6;
            float o[6] = {0.f,0.f,0.f,0.f,0.f,0.f};
            const __nv_bfloat16* vp = vsh + h*Nn*HD_ + d0;
            const float* prow = Ssh + i*65;
            #pragma unroll 4
            for (int j = 0; j < 64; ++j) {
                float pv = prow[j];
                const __nv_bfloat162* v2 = (const __nv_bfloat162*)(vp + j*HD_);
                float2 a = __bfloat1622float2(v2[0]);
                float2 c = __bfloat1622float2(v2[1]);
                float2 e = __bfloat1622float2(v2[2]);
                o[0] += pv*a.x; o[1] += pv*a.y;
                o[2] += pv*c.x; o[3] += pv*c.y;
                o[4] += pv*e.x; o[5] += pv*e.y;
            }
            float ri = rinv[i];
            #pragma unroll
            for (int q = 0; q < 6; ++q)
                aout[(h*HD_ + d0 + q)*64 + i] = o[q]*ri;
        }
        __syncthreads();
    }

    // ===================== proj GEMM + residual + scatter =====================
    {
        float acc[4][12];
        #pragma unroll
        for (int i = 0; i < 4; ++i)
            #pragma unroll
            for (int j = 0; j < 12; ++j) acc[i][j] = 0.f;

        for (int k0 = 0; k0 < Cc; k0 += 16) {
            __syncthreads();
            {
                const int kk   = (tid & 3) << 2;
                const int orow = tid >> 2;
                #pragma unroll
                for (int it = 0; it < 3; ++it) {
                    int ol = it*64 + orow;
                    float4 wv = *(const float4*)&proj_w[ol*Cc + k0 + kk];
                    float* dst = &wsh[kk*196 + ol];
                    dst[0]   = wv.x; dst[196] = wv.y;
                    dst[392] = wv.z; dst[588] = wv.w;
                }
            }
            __syncthreads();
            #pragma unroll 4
            for (int kk = 0; kk < 16; ++kk) {
                float4 xv = *(const float4*)&aout[(k0+kk)*64 + t0];
                const float* wp = &wsh[kk*196 + o0];
                float4 w0 = *(const float4*)(wp);
                float4 w1 = *(const float4*)(wp+4);
                float4 w2 = *(const float4*)(wp+8);
                float wv[12] = {w0.x,w0.y,w0.z,w0.w, w1.x,w1.y,w1.z,w1.w,
                                w2.x,w2.y,w2.z,w2.w};
                float xa[4]  = {xv.x, xv.y, xv.z, xv.w};
                #pragma unroll
                for (int i = 0; i < 4; ++i)
                    #pragma unroll
                    for (int j = 0; j < 12; ++j)
                        acc[i][j] += xa[i]*wv[j];
            }
        }
        // epilogue: +proj bias +residual(x at gathered location), scatter write
        #pragma unroll
        for (int j = 0; j < 12; ++j) {
            int og = o0 + j;
            float bv = proj_b[og];
            float* outc = out + ((b*Cc + og) << 16);
            #pragma unroll
            for (int i = 0; i < 4; ++i) {
                int t = t0 + i;
                int hh = (hbase + (t >> 3)) & 255;
                int ww = (wbase + (t & 7)) & 255;
                outc[(hh << 8) + ww] = acc[i][j] + bv + xsh[og*64 + t];
            }
        }
    }
}

extern "C" void kernel_launch(void* const* d_in, const int* in_sizes, int n_in,
                              void* d_out, int out_size)
{
    const float* x      = (const float*)d_in[0];
    const float* qkv_w  = (const float*)d_in[1];
    const float* qkv_b  = (const float*)d_in[2];
    const float* proj_w = (const float*)d_in[3];
    const float* proj_b = (const float*)d_in[4];
    const float* rpb    = (const float*)d_in[5];
    float* out = (float*)d_out;

    cudaFuncSetAttribute(swin_fused,
                         cudaFuncAttributeMaxDynamicSharedMemorySize, SMEM_BYTES);
    swin_fused<<<4096, TPB, SMEM_BYTES>>>(x, qkv_w, qkv_b, proj_w, proj_b, rpb, out);
}

// round 2
// speedup vs baseline: 3.9231x; 3.9231x over previous
#include <cuda_runtime.h>
#include <cuda_bf16.h>

// Fused shifted-window attention (Swin block), tensor-core version.
// B=4, C=192, H=W=256, ws=8 (N=64), shift=4, heads=8, hd=24.
// One CTA per window (4096 CTAs, 256 threads / 8 warps).
// All GEMMs on mma.sync.m16n8k16.bf16 (fp32 accum). Attention is one warp
// per head, scores fully register-resident (S c-frags repacked to P a-frags).

constexpr int TPB = 256;

// smem layout (bytes)
constexpr int XBF_B  = 0;        // xbf  [64][200] bf16  (tokens x channels)
constexpr int AOUT_B = 25600;    // aout [64][200] bf16  (tokens x channels)
constexpr int WSH_B  = 51200;    // wsh  [64][200] bf16  (n-rows x k)
constexpr int QSH_B  = 76800;    // qsh  [8][64][40] bf16 (head, token, d; d24..31 = 0)
constexpr int KSH_B  = 117760;   // ksh  same
constexpr int VSH_B  = 158720;   // vsh  [8][24][72] bf16 (head, d, token)
constexpr int RPB_B  = 186368;   // rpbt [8][228] f32 (bias table transposed)
constexpr int BIA_B  = 193664;   // bsh  [768] f32 (qkv_b 576 | proj_b 192)
constexpr int SMEM_BYTES = 196736;

__device__ __forceinline__ unsigned sptr(const void* p) {
    return (unsigned)__cvta_generic_to_shared(p);
}
__device__ __forceinline__ void ldmx4(unsigned a, unsigned* r) {
    asm volatile("ldmatrix.sync.aligned.m8n8.x4.shared.b16 {%0,%1,%2,%3}, [%4];"
        : "=r"(r[0]), "=r"(r[1]), "=r"(r[2]), "=r"(r[3]) : "r"(a));
}
__device__ __forceinline__ void ldmx2(unsigned a, unsigned* r) {
    asm volatile("ldmatrix.sync.aligned.m8n8.x2.shared.b16 {%0,%1}, [%2];"
        : "=r"(r[0]), "=r"(r[1]) : "r"(a));
}
__device__ __forceinline__ void mma_bf16(float* c, const unsigned* a, const unsigned* b) {
    asm volatile("mma.sync.aligned.m16n8k16.row.col.f32.bf16.bf16.f32 "
        "{%0,%1,%2,%3}, {%4,%5,%6,%7}, {%8,%9}, {%0,%1,%2,%3};"
        : "+f"(c[0]), "+f"(c[1]), "+f"(c[2]), "+f"(c[3])
        : "r"(a[0]), "r"(a[1]), "r"(a[2]), "r"(a[3]), "r"(b[0]), "r"(b[1]));
}
__device__ __forceinline__ unsigned packbf(float a, float b) {
    __nv_bfloat162 t = __floats2bfloat162_rn(a, b);
    return *(unsigned*)&t;
}

__global__ void __launch_bounds__(TPB, 1)
swin_mma(const float* __restrict__ x,
         const float* __restrict__ qkv_w,
         const float* __restrict__ qkv_b,
         const float* __restrict__ proj_w,
         const float* __restrict__ proj_b,
         const float* __restrict__ rpb,
         float* __restrict__ out)
{
    extern __shared__ char smem[];
    __nv_bfloat16* xbf  = (__nv_bfloat16*)(smem + XBF_B);
    __nv_bfloat16* aoutp= (__nv_bfloat16*)(smem + AOUT_B);
    __nv_bfloat16* wsh  = (__nv_bfloat16*)(smem + WSH_B);
    float* rpbt = (float*)(smem + RPB_B);
    float* bsh  = (float*)(smem + BIA_B);

    const int tid  = threadIdx.x;
    const int lane = tid & 31;
    const int wid  = tid >> 5;
    const int g    = lane >> 2;
    const int tig  = lane & 3;

    const int win = blockIdx.x;
    const int b   = win >> 10;
    const int wr  = (win >> 5) & 31;
    const int wc  = win & 31;
    const int hbase = wr*8 + 4;
    const int wbase = wc*8 + 4;
    const bool er = (wr == 31), ec = (wc == 31);

    const float* xb   = x   + ((b*192) << 16);
    float*       outb = out + ((b*192) << 16);

    // ---------------- prologue loads ----------------
    for (int i = tid; i < 1800; i += TPB)
        rpbt[(i & 7)*228 + (i >> 3)] = rpb[i];
    for (int i = tid; i < 576; i += TPB) bsh[i] = qkv_b[i];
    for (int i = tid; i < 192; i += TPB) bsh[576 + i] = proj_b[i];
    // zero q/k pad cols 24..31 (bytes 48..63 of each 80B row)
    {
        unsigned* qz = (unsigned*)(smem + QSH_B);
        unsigned* kz = (unsigned*)(smem + KSH_B);
        for (int i = tid; i < 2048; i += TPB) {
            int row = i >> 2, c = i & 3;
            qz[row*20 + 12 + c] = 0u;
            kz[row*20 + 12 + c] = 0u;
        }
    }
    // gather shifted window x -> xbf[t][c] (bf16)
    for (int idx = tid; idx < 192*64; idx += TPB) {
        int c = idx >> 6, t = idx & 63;
        int hh = (hbase + (t >> 3)) & 255;
        int ww = (wbase + (t & 7)) & 255;
        xbf[t*200 + c] = __float2bfloat16(xb[(c << 16) + (hh << 8) + ww]);
    }

    // warp grid for GEMMs: 2 (m) x 4 (n)
    const int mg = wid >> 2;        // 0..1 -> rows mg*32
    const int ng = wid & 3;         // 0..3 -> cols ng*16 within 64-pass

    const unsigned aA0 = sptr(smem + XBF_B)  + ((mg*32      + (lane & 15))*200 + (lane >> 4)*8)*2;
    const unsigned aA1 = sptr(smem + XBF_B)  + ((mg*32 + 16 + (lane & 15))*200 + (lane >> 4)*8)*2;
    const unsigned pA0 = sptr(smem + AOUT_B) + ((mg*32      + (lane & 15))*200 + (lane >> 4)*8)*2;
    const unsigned pA1 = sptr(smem + AOUT_B) + ((mg*32 + 16 + (lane & 15))*200 + (lane >> 4)*8)*2;
    const unsigned bB0 = sptr(smem + WSH_B)  + ((ng*16     + (lane & 7))*200 + ((lane >> 3) & 1)*8)*2;
    const unsigned bB1 = sptr(smem + WSH_B)  + ((ng*16 + 8 + (lane & 7))*200 + ((lane >> 3) & 1)*8)*2;

    float4 wreg[12];
    const int ldr = (12*256 > 0) ? 0 : 0; (void)ldr;

    // prefetch W pass 0 (qkv)
    #pragma unroll
    for (int it = 0; it < 12; ++it) {
        int id = it*256 + tid;
        int r = id / 48, cq = id % 48;
        wreg[it] = *(const float4*)(qkv_w + r*192 + cq*4);
    }
    __syncthreads();   // prologue smem ready

    // ================= QKV GEMM: 9 passes of 64 output channels =================
    for (int p = 0; p < 9; ++p) {
        // store prefetched W tile (bf16)
        #pragma unroll
        for (int it = 0; it < 12; ++it) {
            int id = it*256 + tid;
            int r = id / 48, cq = id % 48;
            __nv_bfloat162* d = (__nv_bfloat162*)((char*)wsh + r*400 + cq*8);
            d[0] = __floats2bfloat162_rn(wreg[it].x, wreg[it].y);
            d[1] = __floats2bfloat162_rn(wreg[it].z, wreg[it].w);
        }
        __syncthreads();
        if (p < 8) {
            const float* Wn = qkv_w + (p + 1)*64*192;
            #pragma unroll
            for (int it = 0; it < 12; ++it) {
                int id = it*256 + tid;
                int r = id / 48, cq = id % 48;
                wreg[it] = *(const float4*)(Wn + r*192 + cq*4);
            }
        }
        float acc[2][2][4];
        #pragma unroll
        for (int i = 0; i < 2; ++i)
            #pragma unroll
            for (int j = 0; j < 2; ++j)
                acc[i][j][0]=acc[i][j][1]=acc[i][j][2]=acc[i][j][3]=0.f;

        #pragma unroll
        for (int kt = 0; kt < 12; ++kt) {
            unsigned af[2][4], bf[2][2];
            ldmx4(aA0 + kt*32, af[0]);
            ldmx4(aA1 + kt*32, af[1]);
            ldmx2(bB0 + kt*32, bf[0]);
            ldmx2(bB1 + kt*32, bf[1]);
            mma_bf16(acc[0][0], af[0], bf[0]);
            mma_bf16(acc[0][1], af[0], bf[1]);
            mma_bf16(acc[1][0], af[1], bf[0]);
            mma_bf16(acc[1][1], af[1], bf[1]);
        }
        // epilogue -> q/k/v smem (+bias)
        int oc = p / 3;
        int cbase = (p - oc*3)*64;
        #pragma unroll
        for (int mt = 0; mt < 2; ++mt) {
            #pragma unroll
            for (int j = 0; j < 2; ++j) {
                int cg = cbase + ng*16 + j*8 + 2*tig;
                int hh2 = cg / 24;
                int d  = cg - hh2*24;
                float b0 = bsh[oc*192 + cg], b1 = bsh[oc*192 + cg + 1];
                int r0 = mg*32 + mt*16 + g;
                float c0 = acc[mt][j][0] + b0, c1 = acc[mt][j][1] + b1;
                float c2 = acc[mt][j][2] + b0, c3 = acc[mt][j][3] + b1;
                if (oc == 0) {
                    *(__nv_bfloat162*)(smem + QSH_B + (hh2*64 + r0    )*80 + d*2) = __floats2bfloat162_rn(c0, c1);
                    *(__nv_bfloat162*)(smem + QSH_B + (hh2*64 + r0 + 8)*80 + d*2) = __floats2bfloat162_rn(c2, c3);
                } else if (oc == 1) {
                    *(__nv_bfloat162*)(smem + KSH_B + (hh2*64 + r0    )*80 + d*2) = __floats2bfloat162_rn(c0, c1);
                    *(__nv_bfloat162*)(smem + KSH_B + (hh2*64 + r0 + 8)*80 + d*2) = __floats2bfloat162_rn(c2, c3);
                } else {
                    __nv_bfloat16* vv = (__nv_bfloat16*)(smem + VSH_B) + (hh2*24 + d)*72;
                    vv[r0]          = __float2bfloat16(c0);
                    vv[72 + r0]     = __float2bfloat16(c1);
                    vv[r0 + 8]      = __float2bfloat16(c2);
                    vv[72 + r0 + 8] = __float2bfloat16(c3);
                }
            }
        }
        __syncthreads();   // compute done; q/k/v of this pass visible; wsh reusable
    }

    // ================= attention: one warp per head, register-resident =================
    {
        const int h = wid;
        const float* rp = rpbt + h*228;
        const unsigned qb = sptr(smem + QSH_B) + (h*64 + (lane & 15))*80 + (lane >> 4)*16;
        const unsigned kb = sptr(smem + KSH_B) + (h*64 + (lane & 7))*80 + ((lane >> 3) & 1)*16;
        const unsigned vb = sptr(smem + VSH_B) + (h*24 + (lane & 7))*144 + ((lane >> 3) & 1)*16;
        const float SCALE = 0.2041241452319315f;

        int regjE[2];
        #pragma unroll
        for (int e = 0; e < 2; ++e) {
            int xj = 2*tig + e;
            regjE[e] = ec ? ((xj < 4) ? 1 : 2) : 0;
        }
        const int regiX = ec ? ((g < 4) ? 1 : 2) : 0;

        #pragma unroll
        for (int mp = 0; mp < 2; ++mp) {
            unsigned qf[2][2][4];
            #pragma unroll
            for (int mt = 0; mt < 2; ++mt)
                #pragma unroll
                for (int kq = 0; kq < 2; ++kq)
                    ldmx4(qb + (mp*32 + mt*16)*80 + kq*32, qf[mt][kq]);

            float s[2][8][4];
            #pragma unroll
            for (int jj = 0; jj < 8; ++jj) {
                unsigned kf[2][2];
                ldmx2(kb + jj*640,      kf[0]);
                ldmx2(kb + jj*640 + 32, kf[1]);
                #pragma unroll
                for (int mt = 0; mt < 2; ++mt) {
                    s[mt][jj][0]=s[mt][jj][1]=s[mt][jj][2]=s[mt][jj][3]=0.f;
                    mma_bf16(s[mt][jj], qf[mt][0], kf[0]);
                    mma_bf16(s[mt][jj], qf[mt][1], kf[1]);
                }
            }
            // bias + mask + softmax (rows split over quad lanes, shfl reduce)
            #pragma unroll
            for (int mt = 0; mt < 2; ++mt) {
                int yib = mp*4 + mt*2;
                #pragma unroll
                for (int half = 0; half < 2; ++half) {
                    int yi = yib + half;
                    int regi = (er ? ((yi < 4) ? 3 : 6) : 0) + regiX;
                    float v[16];
                    float mx = -1e30f;
                    #pragma unroll
                    for (int jj = 0; jj < 8; ++jj) {
                        int rjY = er ? ((jj < 4) ? 3 : 6) : 0;
                        #pragma unroll
                        for (int e = 0; e < 2; ++e) {
                            float val = s[mt][jj][half*2 + e]*SCALE;
                            int idx = (yi - jj + 7)*15 + (g - (2*tig + e) + 7);
                            val += rp[idx];
                            if (regi != (rjY + regjE[e])) val -= 100.f;
                            v[jj*2 + e] = val;
                            mx = fmaxf(mx, val);
                        }
                    }
                    mx = fmaxf(mx, __shfl_xor_sync(0xffffffffu, mx, 1));
                    mx = fmaxf(mx, __shfl_xor_sync(0xffffffffu, mx, 2));
                    float sum = 0.f;
                    #pragma unroll
                    for (int q = 0; q < 16; ++q) { v[q] = __expf(v[q] - mx); sum += v[q]; }
                    sum += __shfl_xor_sync(0xffffffffu, sum, 1);
                    sum += __shfl_xor_sync(0xffffffffu, sum, 2);
                    float inv = 1.f / sum;
                    #pragma unroll
                    for (int jj = 0; jj < 8; ++jj) {
                        s[mt][jj][half*2 + 0] = v[jj*2 + 0]*inv;
                        s[mt][jj][half*2 + 1] = v[jj*2 + 1]*inv;
                    }
                }
            }
            // repack P (c-frags) -> a-frags, then O = P @ v
            unsigned pf[2][4][4];
            #pragma unroll
            for (int mt = 0; mt < 2; ++mt)
                #pragma unroll
                for (int kt = 0; kt < 4; ++kt) {
                    pf[mt][kt][0] = packbf(s[mt][2*kt][0],     s[mt][2*kt][1]);
                    pf[mt][kt][1] = packbf(s[mt][2*kt][2],     s[mt][2*kt][3]);
                    pf[mt][kt][2] = packbf(s[mt][2*kt + 1][0], s[mt][2*kt + 1][1]);
                    pf[mt][kt][3] = packbf(s[mt][2*kt + 1][2], s[mt][2*kt + 1][3]);
                }
            float o[2][3][4];
            #pragma unroll
            for (int mt = 0; mt < 2; ++mt)
                #pragma unroll
                for (int vn = 0; vn < 3; ++vn)
                    o[mt][vn][0]=o[mt][vn][1]=o[mt][vn][2]=o[mt][vn][3]=0.f;
            #pragma unroll
            for (int kt = 0; kt < 4; ++kt) {
                #pragma unroll
                for (int vn = 0; vn < 3; ++vn) {
                    unsigned vf[2];
                    ldmx2(vb + vn*1152 + kt*32, vf);
                    mma_bf16(o[0][vn], pf[0][kt], vf);
                    mma_bf16(o[1][vn], pf[1][kt], vf);
                }
            }
            // write O -> aout bf16 [token][h*24 + d]
            #pragma unroll
            for (int mt = 0; mt < 2; ++mt) {
                int r0 = mp*32 + mt*16 + g;
                #pragma unroll
                for (int vn = 0; vn < 3; ++vn) {
                    int col = h*24 + vn*8 + 2*tig;
                    *(__nv_bfloat162*)((char*)aoutp + r0*400 + col*2)
                        = __floats2bfloat162_rn(o[mt][vn][0], o[mt][vn][1]);
                    *(__nv_bfloat162*)((char*)aoutp + (r0 + 8)*400 + col*2)
                        = __floats2bfloat162_rn(o[mt][vn][2], o[mt][vn][3]);
                }
            }
        }
    }

    // prefetch proj W pass 0 before the barrier
    #pragma unroll
    for (int it = 0; it < 12; ++it) {
        int id = it*256 + tid;
        int r = id / 48, cq = id % 48;
        wreg[it] = *(const float4*)(proj_w + r*192 + cq*4);
    }
    __syncthreads();   // aout ready

    // ================= proj GEMM + bias + residual + scatter =================
    for (int p = 0; p < 3; ++p) {
        #pragma unroll
        for (int it = 0; it < 12; ++it) {
            int id = it*256 + tid;
            int r = id / 48, cq = id % 48;
            __nv_bfloat162* d = (__nv_bfloat162*)((char*)wsh + r*400 + cq*8);
            d[0] = __floats2bfloat162_rn(wreg[it].x, wreg[it].y);
            d[1] = __floats2bfloat162_rn(wreg[it].z, wreg[it].w);
        }
        __syncthreads();
        if (p < 2) {
            const float* Wn = proj_w + (p + 1)*64*192;
            #pragma unroll
            for (int it = 0; it < 12; ++it) {
                int id = it*256 + tid;
                int r = id / 48, cq = id % 48;
                wreg[it] = *(const float4*)(Wn + r*192 + cq*4);
            }
        }
        float acc[2][2][4];
        #pragma unroll
        for (int i = 0; i < 2; ++i)
            #pragma unroll
            for (int j = 0; j < 2; ++j)
                acc[i][j][0]=acc[i][j][1]=acc[i][j][2]=acc[i][j][3]=0.f;

        #pragma unroll
        for (int kt = 0; kt < 12; ++kt) {
            unsigned af[2][4], bf[2][2];
            ldmx4(pA0 + kt*32, af[0]);
            ldmx4(pA1 + kt*32, af[1]);
            ldmx2(bB0 + kt*32, bf[0]);
            ldmx2(bB1 + kt*32, bf[1]);
            mma_bf16(acc[0][0], af[0], bf[0]);
            mma_bf16(acc[0][1], af[0], bf[1]);
            mma_bf16(acc[1][0], af[1], bf[0]);
            mma_bf16(acc[1][1], af[1], bf[1]);
        }
        #pragma unroll
        for (int mt = 0; mt < 2; ++mt) {
            #pragma unroll
            for (int j = 0; j < 2; ++j) {
                int ch = p*64 + ng*16 + j*8 + 2*tig;
                float b0 = bsh[576 + ch], b1 = bsh[576 + ch + 1];
                int r0 = mg*32 + mt*16 + g, r1 = r0 + 8;
                int a0 = (((hbase + (r0 >> 3)) & 255) << 8) | ((wbase + (r0 & 7)) & 255);
                int a1 = (((hbase + (r1 >> 3)) & 255) << 8) | ((wbase + (r1 & 7)) & 255);
                const float* xc0 = xb + (ch << 16);
                const float* xc1 = xc0 + 65536;
                float* oc0 = outb + (ch << 16);
                float* oc1 = oc0 + 65536;
                oc0[a0] = acc[mt][j][0] + b0 + xc0[a0];
                oc1[a0] = acc[mt][j][1] + b1 + xc1[a0];
                oc0[a1] = acc[mt][j][2] + b0 + xc0[a1];
                oc1[a1] = acc[mt][j][3] + b1 + xc1[a1];
            }
        }
        if (p < 2) __syncthreads();
    }
}

extern "C" void kernel_launch(void* const* d_in, const int* in_sizes, int n_in,
                              void* d_out, int out_size)
{
    const float* x      = (const float*)d_in[0];
    const float* qkv_w  = (const float*)d_in[1];
    const float* qkv_b  = (const float*)d_in[2];
    const float* proj_w = (const float*)d_in[3];
    const float* proj_b = (const float*)d_in[4];
    const float* rpb    = (const float*)d_in[5];
    float* out = (float*)d_out;

    cudaFuncSetAttribute(swin_mma,
                         cudaFuncAttributeMaxDynamicSharedMemorySize, SMEM_BYTES);
    swin_mma<<<4096, TPB, SMEM_BYTES>>>(x, qkv_w, qkv_b, proj_w, proj_b, rpb, out);
}